// round 8
// baseline (speedup 1.0000x reference)
#include <cuda_runtime.h>
#include <stdint.h>

#define B 64
#define T 512
#define D 384
#define MAX_LEN 4096
#define D4 (D / 4)          // 96 float4 per row
#define ROWS_PER_WARP 4
#define BLOCKS_PER_BATCH 128   // 4096 rows / 32 rows-per-block

// ---------------------------------------------------------------------------
// Single fused kernel. Each block (256 thr, 8 warps) owns 32 consecutive
// output rows of one batch. It recomputes that batch's duration cumsum
// in SMEM (cheap, redundant, fully parallel), binary-searches its rows'
// source indices, then runs the proven warp-per-row gather:
//   live warp   -> 12 batched loads (MLP=12) + 12 streaming stores
//   masked warp -> 12 zero stores, no loads
//   boundary    -> per-row mix (<= 1 warp per batch)
// ---------------------------------------------------------------------------
__global__ __launch_bounds__(256)
void lr_fused(const float4* __restrict__ x,        // [B, T, D4]
              const int*    __restrict__ duration, // [B, T]
              float4*       __restrict__ out,      // [B, MAX_LEN, D4]
              float*        __restrict__ out_tail) // [B] mel_len as f32
{
    __shared__ int s_csum[T];
    __shared__ int s_part[8];

    const int tid    = threadIdx.x;
    const int bid    = blockIdx.x;
    const int b      = bid >> 7;               // / BLOCKS_PER_BATCH
    const int p_base = (bid & (BLOCKS_PER_BATCH - 1)) << 5;  // *32
    const int wid    = tid >> 5;
    const int lane   = tid & 31;

    // ---- block-wide inclusive scan of duration[b][0..511] (2 elems/thread)
    const int d0 = __ldg(&duration[b * T + 2 * tid]);
    const int d1 = __ldg(&duration[b * T + 2 * tid + 1]);

    int inc = d0 + d1;                          // pair sum
    #pragma unroll
    for (int off = 1; off < 32; off <<= 1) {
        int n = __shfl_up_sync(0xffffffffu, inc, off);
        if (lane >= off) inc += n;
    }
    if (lane == 31) s_part[wid] = inc;
    __syncthreads();

    if (tid < 8) {
        int p = s_part[tid];
        #pragma unroll
        for (int off = 1; off < 8; off <<= 1) {
            int n = __shfl_up_sync(0x000000ffu, p, off);
            if (tid >= off) p += n;
        }
        s_part[tid] = p;
    }
    __syncthreads();

    const int base = (wid > 0) ? s_part[wid - 1] : 0;
    const int e    = base + inc;                // csum at element 2*tid+1
    s_csum[2 * tid + 1] = e;
    s_csum[2 * tid]     = e - d1;
    __syncthreads();

    const int mel = s_csum[T - 1];
    if (p_base == 0 && tid == 0) out_tail[b] = (float)mel;

    // ---- gather: this warp's 4 rows are p0 .. p0+3
    const int p0 = p_base + wid * ROWS_PER_WARP;
    const float4* xb   = x   + (long long)b * T * D4;
    float4*       dst0 = out + ((long long)b * MAX_LEN + p0) * D4;
    const float4  z    = make_float4(0.f, 0.f, 0.f, 0.f);

    if (p0 + ROWS_PER_WARP <= mel) {
        // fully live: searches (broadcast LDS), then batched loads, MLP=12
        int idxr[ROWS_PER_WARP];
        #pragma unroll
        for (int r = 0; r < ROWS_PER_WARP; ++r) {
            const int p = p0 + r;
            int c = 0;                          // count of csum entries <= p
            #pragma unroll
            for (int step = 256; step > 0; step >>= 1)
                if (s_csum[c + step - 1] <= p) c += step;
            idxr[r] = c;                        // < T guaranteed (p < mel)
        }

        float4 v[ROWS_PER_WARP][3];
        #pragma unroll
        for (int r = 0; r < ROWS_PER_WARP; ++r) {
            const float4* src = xb + (long long)idxr[r] * D4;
            v[r][0] = __ldg(src + lane);
            v[r][1] = __ldg(src + lane + 32);
            v[r][2] = __ldg(src + lane + 64);
        }
        #pragma unroll
        for (int r = 0; r < ROWS_PER_WARP; ++r) {
            float4* dst = dst0 + (long long)r * D4;
            __stcs(dst + lane,      v[r][0]);
            __stcs(dst + lane + 32, v[r][1]);
            __stcs(dst + lane + 64, v[r][2]);
        }
    } else if (p0 >= mel) {
        // fully masked: pure zero stores
        #pragma unroll
        for (int r = 0; r < ROWS_PER_WARP; ++r) {
            float4* dst = dst0 + (long long)r * D4;
            __stcs(dst + lane,      z);
            __stcs(dst + lane + 32, z);
            __stcs(dst + lane + 64, z);
        }
    } else {
        // boundary warp (at most 1 per batch)
        #pragma unroll
        for (int r = 0; r < ROWS_PER_WARP; ++r) {
            float4* dst = dst0 + (long long)r * D4;
            const int p = p0 + r;
            if (p < mel) {
                int c = 0;
                #pragma unroll
                for (int step = 256; step > 0; step >>= 1)
                    if (s_csum[c + step - 1] <= p) c += step;
                const float4* src = xb + (long long)c * D4;
                __stcs(dst + lane,      __ldg(src + lane));
                __stcs(dst + lane + 32, __ldg(src + lane + 32));
                __stcs(dst + lane + 64, __ldg(src + lane + 64));
            } else {
                __stcs(dst + lane,      z);
                __stcs(dst + lane + 32, z);
                __stcs(dst + lane + 64, z);
            }
        }
    }
}

extern "C" void kernel_launch(void* const* d_in, const int* in_sizes, int n_in,
                              void* d_out, int out_size)
{
    const float* x        = (const float*)d_in[0];
    const int*   duration = (const int*)d_in[1];

    float* out = (float*)d_out;
    float* out_tail = out + (size_t)B * MAX_LEN * D;   // mel_len region (64 floats)

    const int blocks = B * BLOCKS_PER_BATCH;           // 8192
    lr_fused<<<blocks, 256>>>((const float4*)x, duration, (float4*)out, out_tail);
}

// round 9
// speedup vs baseline: 1.1763x; 1.1763x over previous
#include <cuda_runtime.h>
#include <stdint.h>

#define B 64
#define T 512
#define D 384
#define MAX_LEN 4096
#define D4 (D / 4)            // 96 float4 per row
#define ROWS_PER_WARP 4
#define BLOCKS_PER_BATCH 128  // consumer blocks per batch (32 rows each)
#define NPROD B               // producer blocks (one per batch), bids 0..63

// scratch
__device__ int g_idx[B * MAX_LEN];   // valid only for p < mel
__device__ int g_mel[B];
__device__ int g_flag[B];            // 0 -> not ready; zero-init, self-resetting
__device__ int g_done[B];            // consumer completion counters

// ---------------------------------------------------------------------------
// Single kernel, producer/consumer split.
//   bid <  64  : producer for batch bid — scan durations (256 thr x 2 elems),
//                scatter frame indices, publish mel, fence, set flag.
//   bid >= 64  : consumer — poll flag[b] (wave-1 only; later waves see it set),
//                then run the proven R7 warp-per-row gather (MLP=12 hot path).
// Flags/counters self-reset: last consumer of each batch zeroes them, so every
// launch starts clean. Producers are in wave 1 (64 << ~900 wave-1 slots), so
// consumers never deadlock.
// ---------------------------------------------------------------------------
__global__ __launch_bounds__(256)
void lr_prodcons(const float4* __restrict__ x,        // [B, T, D4]
                 const int*    __restrict__ duration, // [B, T]
                 float4*       __restrict__ out,      // [B, MAX_LEN, D4]
                 float*        __restrict__ out_tail) // [B] mel_len as f32
{
    const int tid  = threadIdx.x;
    const int wid  = tid >> 5;
    const int lane = tid & 31;

    if (blockIdx.x < NPROD) {
        // ================= PRODUCER =================
        __shared__ int s_part[8];
        __shared__ int s_mel;
        const int b = blockIdx.x;

        const int d0 = __ldg(&duration[b * T + 2 * tid]);
        const int d1 = __ldg(&duration[b * T + 2 * tid + 1]);

        int inc = d0 + d1;  // pair sum, inclusive scan over pairs
        #pragma unroll
        for (int off = 1; off < 32; off <<= 1) {
            int n = __shfl_up_sync(0xffffffffu, inc, off);
            if (lane >= off) inc += n;
        }
        if (lane == 31) s_part[wid] = inc;
        __syncthreads();

        if (tid < 8) {
            int p = s_part[tid];
            #pragma unroll
            for (int off = 1; off < 8; off <<= 1) {
                int n = __shfl_up_sync(0x000000ffu, p, off);
                if (tid >= off) p += n;
            }
            s_part[tid] = p;
        }
        __syncthreads();

        const int base = (wid > 0) ? s_part[wid - 1] : 0;
        const int e1   = base + inc;        // csum at frame 2*tid+1 (inclusive)
        const int s1   = e1 - d1;           // start of frame 2*tid+1 == csum at 2*tid
        const int s0   = s1 - d0;           // start of frame 2*tid

        int* idx_b = g_idx + b * MAX_LEN;
        for (int p = s0; p < s1; ++p) idx_b[p] = 2 * tid;       // <= 7 iters
        for (int p = s1; p < e1; ++p) idx_b[p] = 2 * tid + 1;   // <= 7 iters

        if (tid == 255) s_mel = e1;
        __syncthreads();

        if (tid == 0) {
            const int mel = s_mel;
            g_mel[b]    = mel;
            out_tail[b] = (float)mel;
            __threadfence();                 // publish idx/mel before flag
            atomicExch(&g_flag[b], 1);
        }
        return;
    }

    // ================= CONSUMER =================
    const int cid    = blockIdx.x - NPROD;
    const int b      = cid >> 7;                       // / BLOCKS_PER_BATCH
    const int p_base = (cid & (BLOCKS_PER_BATCH - 1)) << 5;

    if (tid == 0) {
        while (atomicAdd(&g_flag[b], 0) == 0) __nanosleep(64);
        __threadfence();                     // acquire
    }
    __syncthreads();

    const int mel = g_mel[b];
    const int p0  = p_base + wid * ROWS_PER_WARP;
    const int row0 = b * MAX_LEN + p0;

    const float4* xb   = x   + (long long)b * T * D4;
    float4*       dst0 = out + (long long)row0 * D4;
    const float4  z    = make_float4(0.f, 0.f, 0.f, 0.f);

    if (p0 + ROWS_PER_WARP <= mel) {
        // fully live: batched broadcast idx loads, then 12 loads (MLP=12)
        int idxr[ROWS_PER_WARP];
        #pragma unroll
        for (int r = 0; r < ROWS_PER_WARP; ++r)
            idxr[r] = __ldg(&g_idx[row0 + r]);

        float4 v[ROWS_PER_WARP][3];
        #pragma unroll
        for (int r = 0; r < ROWS_PER_WARP; ++r) {
            const float4* src = xb + (long long)idxr[r] * D4;
            v[r][0] = __ldg(src + lane);
            v[r][1] = __ldg(src + lane + 32);
            v[r][2] = __ldg(src + lane + 64);
        }
        #pragma unroll
        for (int r = 0; r < ROWS_PER_WARP; ++r) {
            float4* dst = dst0 + (long long)r * D4;
            __stcs(dst + lane,      v[r][0]);
            __stcs(dst + lane + 32, v[r][1]);
            __stcs(dst + lane + 64, v[r][2]);
        }
    } else if (p0 >= mel) {
        // fully masked: pure zero stores
        #pragma unroll
        for (int r = 0; r < ROWS_PER_WARP; ++r) {
            float4* dst = dst0 + (long long)r * D4;
            __stcs(dst + lane,      z);
            __stcs(dst + lane + 32, z);
            __stcs(dst + lane + 64, z);
        }
    } else {
        // boundary warp (at most 1 per batch)
        #pragma unroll
        for (int r = 0; r < ROWS_PER_WARP; ++r) {
            float4* dst = dst0 + (long long)r * D4;
            if (p0 + r < mel) {
                const int idx = __ldg(&g_idx[row0 + r]);
                const float4* src = xb + (long long)idx * D4;
                __stcs(dst + lane,      __ldg(src + lane));
                __stcs(dst + lane + 32, __ldg(src + lane + 32));
                __stcs(dst + lane + 64, __ldg(src + lane + 64));
            } else {
                __stcs(dst + lane,      z);
                __stcs(dst + lane + 32, z);
                __stcs(dst + lane + 64, z);
            }
        }
    }

    // self-reset so the next launch starts clean (no extra graph nodes)
    __syncthreads();
    if (tid == 0) {
        const int old = atomicAdd(&g_done[b], 1);
        if (old == BLOCKS_PER_BATCH - 1) {   // last consumer of this batch
            g_done[b] = 0;
            atomicExch(&g_flag[b], 0);
        }
    }
}

extern "C" void kernel_launch(void* const* d_in, const int* in_sizes, int n_in,
                              void* d_out, int out_size)
{
    const float* x        = (const float*)d_in[0];
    const int*   duration = (const int*)d_in[1];

    float* out = (float*)d_out;
    float* out_tail = out + (size_t)B * MAX_LEN * D;   // mel_len region (64 floats)

    const int blocks = NPROD + B * BLOCKS_PER_BATCH;   // 64 + 8192
    lr_prodcons<<<blocks, 256>>>((const float4*)x, duration, (float4*)out, out_tail);
}

// round 12
// speedup vs baseline: 1.1860x; 1.0082x over previous
#include <cuda_runtime.h>
#include <stdint.h>

#define B 64
#define T 512
#define D 384
#define MAX_LEN 4096
#define D4 (D / 4)          // 96 float4 per row
#define ROWS_PER_WARP 4

// scratch: source frame index per output position (valid only for p < mel)
__device__ int g_idx[B * MAX_LEN];
__device__ int g_mel[B];

// ---------------------------------------------------------------------------
// Kernel A: per-batch cumsum (256 thr x 2 frames, shuffle scans), scatter
// frame index, publish mel. Triggers programmatic launch completion early so
// the gather (PDL-dependent) can begin while A drains.
// ---------------------------------------------------------------------------
__global__ __launch_bounds__(256)
void lr_scan_scatter(const int* __restrict__ duration,
                     float* __restrict__ out_tail /* mel_len as f32 */)
{
    __shared__ int s_part[8];
    __shared__ int s_mel;
    const int b    = blockIdx.x;
    const int tid  = threadIdx.x;
    const int wid  = tid >> 5;
    const int lane = tid & 31;

    const int d0 = __ldg(&duration[b * T + 2 * tid]);
    const int d1 = __ldg(&duration[b * T + 2 * tid + 1]);

    int inc = d0 + d1;                      // pair sum, scan over pairs
    #pragma unroll
    for (int off = 1; off < 32; off <<= 1) {
        int n = __shfl_up_sync(0xffffffffu, inc, off);
        if (lane >= off) inc += n;
    }
    if (lane == 31) s_part[wid] = inc;
    __syncthreads();

    if (tid < 8) {
        int p = s_part[tid];
        #pragma unroll
        for (int off = 1; off < 8; off <<= 1) {
            int n = __shfl_up_sync(0x000000ffu, p, off);
            if (tid >= off) p += n;
        }
        s_part[tid] = p;
    }
    __syncthreads();

    const int base = (wid > 0) ? s_part[wid - 1] : 0;
    const int e1   = base + inc;            // inclusive csum at frame 2*tid+1
    const int s1   = e1 - d1;               // start of frame 2*tid+1
    const int s0   = s1 - d0;               // start of frame 2*tid

    int* idx_b = g_idx + b * MAX_LEN;
    for (int p = s0; p < s1; ++p) idx_b[p] = 2 * tid;        // <= 7 iters
    for (int p = s1; p < e1; ++p) idx_b[p] = 2 * tid + 1;    // <= 7 iters

    if (tid == 255) s_mel = e1;
    __syncthreads();
    if (tid == 0) {
        g_mel[b]    = s_mel;
        out_tail[b] = (float)s_mel;
    }

    // make all writes visible, then allow the dependent gather to start
    __threadfence();
    cudaTriggerProgrammaticLaunchCompletion();
}

// ---------------------------------------------------------------------------
// Kernel B: proven R7 warp-per-row gather (4 rows/warp, mel trichotomy,
// MLP=12 hot path), entered through a HW PDL dependency sync.
// rows = B*MAX_LEN = 262144; warps = 65536; blocks(256) = 8192 (exact).
// ---------------------------------------------------------------------------
__global__ __launch_bounds__(256)
void lr_gather(const float4* __restrict__ x,   // [B, T, D4]
               float4* __restrict__ out)        // [B, MAX_LEN, D4]
{
    cudaGridDependencySynchronize();            // HW wait on kernel A

    const int warp = (blockIdx.x * blockDim.x + threadIdx.x) >> 5;
    const int lane = threadIdx.x & 31;
    const int row0 = warp * ROWS_PER_WARP;      // row = b*MAX_LEN + p
    const int b    = row0 >> 12;                // / MAX_LEN
    const int p0   = row0 & (MAX_LEN - 1);
    const int mel  = __ldg(&g_mel[b]);

    const float4 z = make_float4(0.f, 0.f, 0.f, 0.f);
    float4* dst0 = out + (long long)row0 * D4;
    const float4* xb = x + (long long)b * T * D4;

    if (p0 + ROWS_PER_WARP <= mel) {
        // fully live: batched loads, MLP = 12
        int idxr[ROWS_PER_WARP];
        #pragma unroll
        for (int r = 0; r < ROWS_PER_WARP; ++r)
            idxr[r] = __ldg(&g_idx[row0 + r]);

        float4 v[ROWS_PER_WARP][3];
        #pragma unroll
        for (int r = 0; r < ROWS_PER_WARP; ++r) {
            const float4* src = xb + (long long)idxr[r] * D4;
            v[r][0] = __ldg(src + lane);
            v[r][1] = __ldg(src + lane + 32);
            v[r][2] = __ldg(src + lane + 64);
        }
        #pragma unroll
        for (int r = 0; r < ROWS_PER_WARP; ++r) {
            float4* dst = dst0 + (long long)r * D4;
            __stcs(dst + lane,      v[r][0]);
            __stcs(dst + lane + 32, v[r][1]);
            __stcs(dst + lane + 64, v[r][2]);
        }
    } else if (p0 >= mel) {
        // fully masked: pure zero stores, no loads
        #pragma unroll
        for (int r = 0; r < ROWS_PER_WARP; ++r) {
            float4* dst = dst0 + (long long)r * D4;
            __stcs(dst + lane,      z);
            __stcs(dst + lane + 32, z);
            __stcs(dst + lane + 64, z);
        }
    } else {
        // boundary warp (at most 1 per batch)
        #pragma unroll
        for (int r = 0; r < ROWS_PER_WARP; ++r) {
            float4* dst = dst0 + (long long)r * D4;
            if (p0 + r < mel) {
                const int idx = __ldg(&g_idx[row0 + r]);
                const float4* src = xb + (long long)idx * D4;
                __stcs(dst + lane,      __ldg(src + lane));
                __stcs(dst + lane + 32, __ldg(src + lane + 32));
                __stcs(dst + lane + 64, __ldg(src + lane + 64));
            } else {
                __stcs(dst + lane,      z);
                __stcs(dst + lane + 32, z);
                __stcs(dst + lane + 64, z);
            }
        }
    }
}

extern "C" void kernel_launch(void* const* d_in, const int* in_sizes, int n_in,
                              void* d_out, int out_size)
{
    const float* x        = (const float*)d_in[0];
    const int*   duration = (const int*)d_in[1];

    float* out = (float*)d_out;
    float* out_tail = out + (size_t)B * MAX_LEN * D;   // mel_len region (64 floats)

    // Kernel A: plain launch on the capture stream
    lr_scan_scatter<<<B, 256>>>(duration, out_tail);

    // Kernel B: PDL launch — overlaps its launch/prologue with A's tail
    cudaLaunchConfig_t cfg = {};
    cfg.gridDim  = dim3(8192, 1, 1);          // 65536 warps * 32 / 256
    cfg.blockDim = dim3(256, 1, 1);
    cfg.dynamicSmemBytes = 0;
    cfg.stream = 0;

    cudaLaunchAttribute attr[1];
    attr[0].id = cudaLaunchAttributeProgrammaticStreamSerialization;
    attr[0].val.programmaticStreamSerializationAllowed = 1;
    cfg.attrs = attr;
    cfg.numAttrs = 1;

    cudaLaunchKernelEx(&cfg, lr_gather, (const float4*)x, (float4*)out);
}

// round 13
// speedup vs baseline: 1.2399x; 1.0455x over previous
#include <cuda_runtime.h>
#include <stdint.h>

#define B 64
#define T 512
#define D 384
#define MAX_LEN 4096
#define D4 (D / 4)            // 96 float4 per row
#define ROWS_PER_WARP 4
#define BLOCKS_PER_BATCH 128  // 4096 rows / 32 rows-per-block

// ---------------------------------------------------------------------------
// Single fused kernel, fully self-sufficient blocks (no inter-block sync, no
// global scratch). Each block (256 thr, 8 warps) owns 32 output rows of one
// batch:
//   1. coalesced load of the batch's 512 durations (2/thread; L2-hot, shared
//      by 128 blocks)
//   2. pair-wise shuffle scan -> each thread knows frames 2t,2t+1 output
//      ranges [s0,s1), [s1,e1), and mel = total
//   3. WINDOW SCATTER: intersect ranges with [p_base, p_base+32), write frame
//      ids straight into s_win[32]  (<= 32 shared writes/block, no search)
//   4. proven warp-per-row gather: live warps = 12 batched loads (MLP=12) +
//      12 streaming stores; masked warps = 12 zero stores; boundary mixes.
// ---------------------------------------------------------------------------
__global__ __launch_bounds__(256)
void lr_fused(const float4* __restrict__ x,        // [B, T, D4]
              const int*    __restrict__ duration, // [B, T]
              float4*       __restrict__ out,      // [B, MAX_LEN, D4]
              float*        __restrict__ out_tail) // [B] mel_len as f32
{
    __shared__ int s_part[8];
    __shared__ int s_win[32];   // frame index per row in this block's window

    const int tid    = threadIdx.x;
    const int bid    = blockIdx.x;
    const int b      = bid >> 7;                            // / BLOCKS_PER_BATCH
    const int p_base = (bid & (BLOCKS_PER_BATCH - 1)) << 5; // * 32
    const int wid    = tid >> 5;
    const int lane   = tid & 31;

    // ---- pair-wise block scan of duration[b][0..511] ----
    const int d0 = __ldg(&duration[b * T + 2 * tid]);
    const int d1 = __ldg(&duration[b * T + 2 * tid + 1]);

    int inc = d0 + d1;                       // pair sum, scanned over pairs
    #pragma unroll
    for (int off = 1; off < 32; off <<= 1) {
        int n = __shfl_up_sync(0xffffffffu, inc, off);
        if (lane >= off) inc += n;
    }
    if (lane == 31) s_part[wid] = inc;
    __syncthreads();

    if (tid < 8) {
        int p = s_part[tid];
        #pragma unroll
        for (int off = 1; off < 8; off <<= 1) {
            int n = __shfl_up_sync(0x000000ffu, p, off);
            if (tid >= off) p += n;
        }
        s_part[tid] = p;
    }
    __syncthreads();

    const int base = (wid > 0) ? s_part[wid - 1] : 0;
    const int e1   = base + inc;             // inclusive csum at frame 2*tid+1
    const int s1   = e1 - d1;                // start of frame 2*tid+1
    const int s0   = s1 - d0;                // start of frame 2*tid
    const int mel  = s_part[7];              // total expanded length

    // ---- window scatter: rows [p_base, p_base+32) get their frame ids ----
    {
        const int wlo = p_base, whi = p_base + 32;
        int lo = s0 > wlo ? s0 : wlo;
        int hi = s1 < whi ? s1 : whi;
        for (int p = lo; p < hi; ++p) s_win[p - p_base] = 2 * tid;
        lo = s1 > wlo ? s1 : wlo;
        hi = e1 < whi ? e1 : whi;
        for (int p = lo; p < hi; ++p) s_win[p - p_base] = 2 * tid + 1;
    }

    if (p_base == 0 && tid == 0) out_tail[b] = (float)mel;
    __syncthreads();

    // ---- gather: this warp's rows p0 .. p0+3 ----
    const int p0 = p_base + wid * ROWS_PER_WARP;
    const float4* xb   = x   + (long long)b * T * D4;
    float4*       dst0 = out + ((long long)b * MAX_LEN + p0) * D4;
    const float4  z    = make_float4(0.f, 0.f, 0.f, 0.f);

    if (p0 + ROWS_PER_WARP <= mel) {
        // fully live: LDS-broadcast indices, then 12 batched loads (MLP=12)
        int idxr[ROWS_PER_WARP];
        #pragma unroll
        for (int r = 0; r < ROWS_PER_WARP; ++r)
            idxr[r] = s_win[(p0 - p_base) + r];

        float4 v[ROWS_PER_WARP][3];
        #pragma unroll
        for (int r = 0; r < ROWS_PER_WARP; ++r) {
            const float4* src = xb + (long long)idxr[r] * D4;
            v[r][0] = __ldg(src + lane);
            v[r][1] = __ldg(src + lane + 32);
            v[r][2] = __ldg(src + lane + 64);
        }
        #pragma unroll
        for (int r = 0; r < ROWS_PER_WARP; ++r) {
            float4* dst = dst0 + (long long)r * D4;
            __stcs(dst + lane,      v[r][0]);
            __stcs(dst + lane + 32, v[r][1]);
            __stcs(dst + lane + 64, v[r][2]);
        }
    } else if (p0 >= mel) {
        // fully masked: pure zero stores, no loads
        #pragma unroll
        for (int r = 0; r < ROWS_PER_WARP; ++r) {
            float4* dst = dst0 + (long long)r * D4;
            __stcs(dst + lane,      z);
            __stcs(dst + lane + 32, z);
            __stcs(dst + lane + 64, z);
        }
    } else {
        // boundary warp (at most 1 per batch)
        #pragma unroll
        for (int r = 0; r < ROWS_PER_WARP; ++r) {
            float4* dst = dst0 + (long long)r * D4;
            if (p0 + r < mel) {
                const int idx = s_win[(p0 - p_base) + r];
                const float4* src = xb + (long long)idx * D4;
                __stcs(dst + lane,      __ldg(src + lane));
                __stcs(dst + lane + 32, __ldg(src + lane + 32));
                __stcs(dst + lane + 64, __ldg(src + lane + 64));
            } else {
                __stcs(dst + lane,      z);
                __stcs(dst + lane + 32, z);
                __stcs(dst + lane + 64, z);
            }
        }
    }
}

extern "C" void kernel_launch(void* const* d_in, const int* in_sizes, int n_in,
                              void* d_out, int out_size)
{
    const float* x        = (const float*)d_in[0];
    const int*   duration = (const int*)d_in[1];

    float* out = (float*)d_out;
    float* out_tail = out + (size_t)B * MAX_LEN * D;   // mel_len region (64 floats)

    const int blocks = B * BLOCKS_PER_BATCH;           // 8192
    lr_fused<<<blocks, 256>>>((const float4*)x, duration, (float4*)out, out_tail);
}